// round 1
// baseline (speedup 1.0000x reference)
#include <cuda_runtime.h>
#include <math.h>

#define HID 64
#define EMBD 32
#define NMAX 393216   // 768 * 512 upper bound on total nodes

// scratch (allocation-free rule: device globals)
__device__ float g_bufA[NMAX * HID];
__device__ float g_bufB[NMAX * HID];
__device__ float g_bufG[NMAX * HID];
__device__ float g_embv[NMAX * EMBD];
__device__ float g_logit[NMAX];

// ---------------- input layer: h = relu(x @ w_in + b_in), x:[N,8] ----------------
__global__ void k_in(const float* __restrict__ x, const float* __restrict__ w,
                     const float* __restrict__ b, float* __restrict__ h, int N) {
    __shared__ float ws[8 * 64];
    __shared__ float bs[64];
    __shared__ float xs[4][9];
    int tid = threadIdx.x;
    for (int t = tid; t < 512; t += 256) ws[t] = w[t];
    if (tid < 64) bs[tid] = b[tid];
    int i0 = blockIdx.x * 4;
    if (tid < 32) {
        int n = tid / 8, k = tid % 8;
        int i = i0 + n;
        xs[n][k] = (i < N) ? x[i * 8 + k] : 0.f;
    }
    __syncthreads();
    int n = tid >> 6, j = tid & 63;
    int i = i0 + n;
    if (i >= N) return;
    float acc = bs[j];
#pragma unroll
    for (int k = 0; k < 8; k++) acc += xs[n][k] * ws[k * 64 + j];
    h[i * 64 + j] = fmaxf(acc, 0.f);
}

// ---------------- g = h @ W (64x64), no activation ----------------
__global__ void k_nbmm(const float* __restrict__ A, const float* __restrict__ W,
                       float* __restrict__ C, int N) {
    __shared__ float ws[64 * 64];
    __shared__ float as[16][65];
    int tid = threadIdx.x;
    const float4* W4 = (const float4*)W;
    float4* ws4 = (float4*)ws;
#pragma unroll
    for (int t = 0; t < 4; t++) ws4[tid + t * 256] = W4[tid + t * 256];
    int i0 = blockIdx.x * 16;
#pragma unroll
    for (int t = 0; t < 4; t++) {
        int idx = tid + t * 256;
        int n = idx >> 6, k = idx & 63;
        int i = i0 + n;
        as[n][k] = (i < N) ? A[i * 64 + k] : 0.f;
    }
    __syncthreads();
    int n = tid >> 4, jg = tid & 15;
    int i = i0 + n;
    if (i >= N) return;
    float4 acc = {0.f, 0.f, 0.f, 0.f};
#pragma unroll
    for (int k = 0; k < 64; k++) {
        float a = as[n][k];
        float4 w4 = *(const float4*)&ws[k * 64 + jg * 4];
        acc.x += a * w4.x; acc.y += a * w4.y; acc.z += a * w4.z; acc.w += a * w4.w;
    }
    *(float4*)&C[i * 64 + jg * 4] = acc;
}

// ------- fused layer: h_new = relu(h@w_self + b + sum_e relu(g[src_e] + ea_e@w_edge)) -------
// relies on dst == repeat(arange(N),4): node i's edges are [4i, 4i+4)
__global__ void k_layer(const float* __restrict__ H, const float* __restrict__ G,
                        const float* __restrict__ Wself, const float* __restrict__ Wedge,
                        const float* __restrict__ bl, const int* __restrict__ src,
                        const float* __restrict__ ea, float* __restrict__ Hout, int N) {
    __shared__ float ws[64 * 64];
    __shared__ float as[16][65];
    __shared__ float we[4 * 64];
    __shared__ float bs[64];
    __shared__ float eas[256];  // 16 nodes * 4 edges * 4 attrs
    __shared__ int ss[64];      // 16 nodes * 4 edges src index
    int tid = threadIdx.x;
    const float4* W4 = (const float4*)Wself;
    float4* ws4 = (float4*)ws;
#pragma unroll
    for (int t = 0; t < 4; t++) ws4[tid + t * 256] = W4[tid + t * 256];
    we[tid] = Wedge[tid];
    if (tid < 64) bs[tid] = bl[tid];
    int i0 = blockIdx.x * 16;
    int e0 = i0 * 4;
    int E = N * 4;
    {
        int eglob = e0 + (tid >> 2);
        eas[tid] = (eglob < E) ? ea[e0 * 4 + tid] : 0.f;
    }
    if (tid < 64) {
        int eglob = e0 + tid;
        ss[tid] = (eglob < E) ? src[eglob] : 0;
    }
#pragma unroll
    for (int t = 0; t < 4; t++) {
        int idx = tid + t * 256;
        int n = idx >> 6, k = idx & 63;
        int i = i0 + n;
        as[n][k] = (i < N) ? H[i * 64 + k] : 0.f;
    }
    __syncthreads();
    int n = tid >> 4, jg = tid & 15;
    int i = i0 + n;
    if (i >= N) return;
    float4 acc = {0.f, 0.f, 0.f, 0.f};
#pragma unroll
    for (int k = 0; k < 64; k++) {
        float a = as[n][k];
        float4 w4 = *(const float4*)&ws[k * 64 + jg * 4];
        acc.x += a * w4.x; acc.y += a * w4.y; acc.z += a * w4.z; acc.w += a * w4.w;
    }
    float4 wer[4];
#pragma unroll
    for (int d = 0; d < 4; d++) wer[d] = *(const float4*)&we[d * 64 + jg * 4];
    float4 agg = {0.f, 0.f, 0.f, 0.f};
#pragma unroll
    for (int el = 0; el < 4; el++) {
        int s = ss[n * 4 + el];
        float4 m = *(const float4*)&G[(long)s * 64 + jg * 4];
#pragma unroll
        for (int d = 0; d < 4; d++) {
            float e = eas[(n * 4 + el) * 4 + d];
            m.x += e * wer[d].x; m.y += e * wer[d].y;
            m.z += e * wer[d].z; m.w += e * wer[d].w;
        }
        agg.x += fmaxf(m.x, 0.f); agg.y += fmaxf(m.y, 0.f);
        agg.z += fmaxf(m.z, 0.f); agg.w += fmaxf(m.w, 0.f);
    }
    float4 b4 = *(const float4*)&bs[jg * 4];
    float4 o;
    o.x = fmaxf(acc.x + agg.x + b4.x, 0.f);
    o.y = fmaxf(acc.y + agg.y + b4.y, 0.f);
    o.z = fmaxf(acc.z + agg.z + b4.z, 0.f);
    o.w = fmaxf(acc.w + agg.w + b4.w, 0.f);
    *(float4*)&Hout[i * 64 + jg * 4] = o;
}

// -------- emb = h@w_out + b_out ; loc_logit = relu(emb@la_w1+la_b1)@la_w2 + la_b2 --------
__global__ void k_emb(const float* __restrict__ H, const float* __restrict__ Wout,
                      const float* __restrict__ bout, const float* __restrict__ law1,
                      const float* __restrict__ lab1, const float* __restrict__ law2,
                      const float* __restrict__ lab2, float* __restrict__ emb,
                      float* __restrict__ logit, int N) {
    __shared__ float wo[64 * 32];
    __shared__ float w1[32 * 32];
    __shared__ float bo[32], b1[32], w2[32];
    __shared__ float as[8][65];
    __shared__ float es[8][33];
    int tid = threadIdx.x;
    for (int t = tid; t < 2048; t += 256) wo[t] = Wout[t];
    for (int t = tid; t < 1024; t += 256) w1[t] = law1[t];
    if (tid < 32) { bo[tid] = bout[tid]; b1[tid] = lab1[tid]; w2[tid] = law2[tid]; }
    int i0 = blockIdx.x * 8;
#pragma unroll
    for (int t = 0; t < 2; t++) {
        int idx = tid + t * 256;
        int n = idx >> 6, k = idx & 63;
        int i = i0 + n;
        as[n][k] = (i < N) ? H[i * 64 + k] : 0.f;
    }
    __syncthreads();
    int n = tid >> 5, j = tid & 31;  // one warp per node
    int i = i0 + n;
    float e = bo[j];
#pragma unroll
    for (int k = 0; k < 64; k++) e += as[n][k] * wo[k * 32 + j];
    es[n][j] = e;
    if (i < N) emb[(long)i * 32 + j] = e;
    __syncwarp();
    float a = b1[j];
#pragma unroll
    for (int k = 0; k < 32; k++) a += es[n][k] * w1[k * 32 + j];
    a = fmaxf(a, 0.f);
    float v = a * w2[j];
#pragma unroll
    for (int o = 16; o > 0; o >>= 1) v += __shfl_down_sync(0xffffffffu, v, o);
    if (j == 0 && i < N) logit[i] = v + lab2[0];
}

// -------- per-graph heads: one block per graph --------
__global__ void k_heads(const float* __restrict__ emb, const float* __restrict__ logit,
                        const int* __restrict__ ptr, const int* __restrict__ loc,
                        const int* __restrict__ mut,
                        const float* __restrict__ maw1, const float* __restrict__ mab1,
                        const float* __restrict__ maw2, const float* __restrict__ mab2,
                        const float* __restrict__ lcw1, const float* __restrict__ lcb1,
                        const float* __restrict__ lcw2, const float* __restrict__ lcb2,
                        const float* __restrict__ mcw1, const float* __restrict__ mcb1,
                        const float* __restrict__ mcw2, const float* __restrict__ mcb2,
                        float* __restrict__ out, int B) {
    __shared__ float ls[768];
    __shared__ float red[256];
    __shared__ float red2[256];
    __shared__ float pool[8][33];
    __shared__ float poolr[32];
    __shared__ float selr[32];
    __shared__ float hidm[32];
    int b = blockIdx.x, tid = threadIdx.x;
    int i0 = ptr[b], i1 = ptr[b + 1];
    int cnt = i1 - i0;
    for (int t = tid; t < cnt; t += 256) ls[t] = logit[i0 + t];
    // pooled sum of emb rows
    int j = tid & 31, r = tid >> 5;
    float p = 0.f;
    for (int t = r; t < cnt; t += 8) p += emb[(long)(i0 + t) * 32 + j];
    pool[r][j] = p;
    __syncthreads();
    if (tid < 32) {
        float s = 0.f;
#pragma unroll
        for (int rr = 0; rr < 8; rr++) s += pool[rr][tid];
        poolr[tid] = s;
    }
    // segment max
    float m = -1e30f;
    for (int t = tid; t < cnt; t += 256) m = fmaxf(m, ls[t]);
    red[tid] = m;
    __syncthreads();
    for (int s = 128; s > 0; s >>= 1) {
        if (tid < s) red[tid] = fmaxf(red[tid], red[tid + s]);
        __syncthreads();
    }
    m = red[0];
    __syncthreads();
    // Z and sum(ez*zsh)
    float z = 0.f, sz = 0.f;
    for (int t = tid; t < cnt; t += 256) {
        float zz = ls[t] - m;
        float e = expf(zz);
        z += e; sz += e * zz;
    }
    red[tid] = z; red2[tid] = sz;
    __syncthreads();
    for (int s = 128; s > 0; s >>= 1) {
        if (tid < s) { red[tid] += red[tid + s]; red2[tid] += red2[tid + s]; }
        __syncthreads();
    }
    float Z = red[0], S = red2[0];
    float logZ = logf(Z);
    int gl = i0 + loc[b];
    if (tid < 32) selr[tid] = emb[(long)gl * 32 + tid];
    __syncthreads();
    // mutation actor hidden
    if (tid < 32) {
        float h1 = mab1[tid];
#pragma unroll
        for (int k = 0; k < 32; k++) h1 += selr[k] * maw1[k * 32 + tid];
        hidm[tid] = fmaxf(h1, 0.f);
    }
    __syncthreads();
    if (tid == 0) {
        float lg[4];
        float mm = -1e30f;
#pragma unroll
        for (int q = 0; q < 4; q++) {
            float s = mab2[q];
            for (int k = 0; k < 32; k++) s += hidm[k] * maw2[k * 4 + q];
            lg[q] = s; mm = fmaxf(mm, s);
        }
        float se = 0.f;
#pragma unroll
        for (int q = 0; q < 4; q++) se += expf(lg[q] - mm);
        float lse = logf(se) + mm;
        float ent = 0.f;
#pragma unroll
        for (int q = 0; q < 4; q++) {
            float lp = lg[q] - lse;
            ent -= expf(lp) * lp;
        }
        out[1 * B + b] = lg[mut[b]] - lse;
        out[3 * B + b] = ent;
        out[0 * B + b] = (ls[loc[b]] - m) - logZ;
        out[2 * B + b] = logZ - S / Z;
    }
    if (tid < 32) {
        // location critic (pooled)
        float h2 = lcb1[tid];
#pragma unroll
        for (int k = 0; k < 32; k++) h2 += poolr[k] * lcw1[k * 32 + tid];
        h2 = fmaxf(h2, 0.f);
        float v = h2 * lcw2[tid];
#pragma unroll
        for (int o = 16; o > 0; o >>= 1) v += __shfl_down_sync(0xffffffffu, v, o);
        if (tid == 0) out[4 * B + b] = v + lcb2[0];
        // mutation critic (selected node)
        float h3 = mcb1[tid];
#pragma unroll
        for (int k = 0; k < 32; k++) h3 += selr[k] * mcw1[k * 32 + tid];
        h3 = fmaxf(h3, 0.f);
        float v2 = h3 * mcw2[tid];
#pragma unroll
        for (int o = 16; o > 0; o >>= 1) v2 += __shfl_down_sync(0xffffffffu, v2, o);
        if (tid == 0) out[5 * B + b] = v2 + mcb2[0];
    }
}

extern "C" void kernel_launch(void* const* d_in, const int* in_sizes, int n_in,
                              void* d_out, int out_size) {
    const float* x      = (const float*)d_in[0];
    const float* eattr  = (const float*)d_in[1];
    const int*   ei     = (const int*)d_in[2];
    const int*   ptr    = (const int*)d_in[4];
    const int*   loc    = (const int*)d_in[5];
    const int*   mut    = (const int*)d_in[6];
    const float* w_in   = (const float*)d_in[7];
    const float* b_in   = (const float*)d_in[8];
    const float* w_self = (const float*)d_in[9];
    const float* w_nb   = (const float*)d_in[10];
    const float* w_edge = (const float*)d_in[11];
    const float* b_l    = (const float*)d_in[12];
    const float* w_out  = (const float*)d_in[13];
    const float* b_out  = (const float*)d_in[14];
    const float* la_w1  = (const float*)d_in[15];
    const float* la_b1  = (const float*)d_in[16];
    const float* la_w2  = (const float*)d_in[17];
    const float* la_b2  = (const float*)d_in[18];
    const float* ma_w1  = (const float*)d_in[19];
    const float* ma_b1  = (const float*)d_in[20];
    const float* ma_w2  = (const float*)d_in[21];
    const float* ma_b2  = (const float*)d_in[22];
    const float* lc_w1  = (const float*)d_in[23];
    const float* lc_b1  = (const float*)d_in[24];
    const float* lc_w2  = (const float*)d_in[25];
    const float* lc_b2  = (const float*)d_in[26];
    const float* mc_w1  = (const float*)d_in[27];
    const float* mc_b1  = (const float*)d_in[28];
    const float* mc_w2  = (const float*)d_in[29];
    const float* mc_b2  = (const float*)d_in[30];
    float* out = (float*)d_out;

    int N = in_sizes[0] / 8;
    int B = in_sizes[4] - 1;
    const int* src = ei;  // edge_index row 0

    float *hA, *hB, *gG, *embp, *lg;
    cudaGetSymbolAddress((void**)&hA, g_bufA);
    cudaGetSymbolAddress((void**)&hB, g_bufB);
    cudaGetSymbolAddress((void**)&gG, g_bufG);
    cudaGetSymbolAddress((void**)&embp, g_embv);
    cudaGetSymbolAddress((void**)&lg, g_logit);

    float* hin = hA;
    float* hout = hB;
    k_in<<<(N + 3) / 4, 256>>>(x, w_in, b_in, hin, N);
    for (int l = 0; l < 3; l++) {
        k_nbmm<<<(N + 15) / 16, 256>>>(hin, w_nb + l * 4096, gG, N);
        k_layer<<<(N + 15) / 16, 256>>>(hin, gG, w_self + l * 4096, w_edge + l * 256,
                                        b_l + l * 64, src, eattr, hout, N);
        float* t = hin; hin = hout; hout = t;
    }
    k_emb<<<(N + 7) / 8, 256>>>(hin, w_out, b_out, la_w1, la_b1, la_w2, la_b2,
                                embp, lg, N);
    k_heads<<<B, 256>>>(embp, lg, ptr, loc, mut,
                        ma_w1, ma_b1, ma_w2, ma_b2,
                        lc_w1, lc_b1, lc_w2, lc_b2,
                        mc_w1, mc_b1, mc_w2, mc_b2,
                        out, B);
}

// round 3
// speedup vs baseline: 1.7737x; 1.7737x over previous
#include <cuda_runtime.h>
#include <math.h>

#define HID 64
#define EMBD 32
#define NMAX 393216   // 768 * 512 upper bound on total nodes

// scratch (allocation-free rule: device globals)
__device__ float g_bufA[NMAX * HID];
__device__ float g_bufB[NMAX * HID];
__device__ float g_bufG[NMAX * HID];
__device__ float g_embv[NMAX * EMBD];
__device__ float g_logit[NMAX];

typedef unsigned long long ull;

// packed fp32x2 helpers (Blackwell)
#define FFMA2(d, a, b) asm("fma.rn.f32x2 %0, %1, %2, %0;" : "+l"(d) : "l"(a), "l"(b))
#define PACKF2(d, x)   asm("mov.b64 %0, {%1, %1};" : "=l"(d) : "f"(x))
#define UNPACK2(lo, hi, p) asm("mov.b64 {%0, %1}, %2;" : "=f"(lo), "=f"(hi) : "l"(p))

// ---------------- input layer: h = relu(x @ w_in + b_in), x:[N,8] ----------------
__global__ void k_in(const float* __restrict__ x, const float* __restrict__ w,
                     const float* __restrict__ b, float* __restrict__ h, int N) {
    __shared__ float ws[8 * 64];
    __shared__ float bs[64];
    __shared__ float xs[4][9];
    int tid = threadIdx.x;
    for (int t = tid; t < 512; t += 256) ws[t] = w[t];
    if (tid < 64) bs[tid] = b[tid];
    int i0 = blockIdx.x * 4;
    if (tid < 32) {
        int n = tid / 8, k = tid % 8;
        int i = i0 + n;
        xs[n][k] = (i < N) ? x[i * 8 + k] : 0.f;
    }
    __syncthreads();
    int n = tid >> 6, j = tid & 63;
    int i = i0 + n;
    if (i >= N) return;
    float acc = bs[j];
#pragma unroll
    for (int k = 0; k < 8; k++) acc += xs[n][k] * ws[k * 64 + j];
    h[i * 64 + j] = fmaxf(acc, 0.f);
}

// Load a 64-row x 64-col tile of A (row-major) into transposed smem at[k][row].
__device__ __forceinline__ void load_a_tile_T(const float* __restrict__ A, int i0, int N,
                                              float (*at)[68], int tid) {
    int lrow = tid >> 1;
    int q0 = (tid & 1) * 8;
    int i = i0 + lrow;
#pragma unroll
    for (int q = 0; q < 8; q++) {
        float4 v;
        if (i < N) v = *(const float4*)&A[(size_t)i * 64 + (q0 + q) * 4];
        else v = make_float4(0.f, 0.f, 0.f, 0.f);
        int kb = (q0 + q) * 4;
        at[kb + 0][lrow] = v.x;
        at[kb + 1][lrow] = v.y;
        at[kb + 2][lrow] = v.z;
        at[kb + 3][lrow] = v.w;
    }
}

// ---------------- g = h @ W (64x64), register-tiled, packed f32x2 ----------------
__global__ void __launch_bounds__(128) k_nbmm(const float* __restrict__ A,
                                              const float* __restrict__ W,
                                              float* __restrict__ C, int N) {
    __shared__ float at[64][68];
    __shared__ float ws[64 * 64];
    int tid = threadIdx.x;
    {
        const float4* W4 = (const float4*)W;
        float4* ws4 = (float4*)ws;
#pragma unroll
        for (int t = 0; t < 8; t++) ws4[tid + t * 128] = W4[tid + t * 128];
    }
    int i0 = blockIdx.x * 64;
    load_a_tile_T(A, i0, N, at, tid);
    __syncthreads();

    int tr = tid >> 4, tc = tid & 15;
    int r0 = tr * 8;
    ull acc[4][4];
#pragma unroll
    for (int p = 0; p < 4; p++)
#pragma unroll
        for (int j = 0; j < 4; j++) acc[p][j] = 0ULL;

#pragma unroll 8
    for (int k = 0; k < 64; k++) {
        const ull* ap = (const ull*)&at[k][r0];
        ull a0 = ap[0], a1 = ap[1], a2 = ap[2], a3 = ap[3];
        float4 w4 = *(const float4*)&ws[k * 64 + tc * 4];
        ull wx, wy, wz, ww;
        PACKF2(wx, w4.x); PACKF2(wy, w4.y); PACKF2(wz, w4.z); PACKF2(ww, w4.w);
        FFMA2(acc[0][0], a0, wx); FFMA2(acc[0][1], a0, wy);
        FFMA2(acc[0][2], a0, wz); FFMA2(acc[0][3], a0, ww);
        FFMA2(acc[1][0], a1, wx); FFMA2(acc[1][1], a1, wy);
        FFMA2(acc[1][2], a1, wz); FFMA2(acc[1][3], a1, ww);
        FFMA2(acc[2][0], a2, wx); FFMA2(acc[2][1], a2, wy);
        FFMA2(acc[2][2], a2, wz); FFMA2(acc[2][3], a2, ww);
        FFMA2(acc[3][0], a3, wx); FFMA2(acc[3][1], a3, wy);
        FFMA2(acc[3][2], a3, wz); FFMA2(acc[3][3], a3, ww);
    }

#pragma unroll
    for (int p = 0; p < 4; p++) {
        float lo0, hi0, lo1, hi1, lo2, hi2, lo3, hi3;
        UNPACK2(lo0, hi0, acc[p][0]); UNPACK2(lo1, hi1, acc[p][1]);
        UNPACK2(lo2, hi2, acc[p][2]); UNPACK2(lo3, hi3, acc[p][3]);
        int ia = i0 + r0 + 2 * p;
        if (ia < N)     *(float4*)&C[(size_t)ia * 64 + tc * 4] = make_float4(lo0, lo1, lo2, lo3);
        if (ia + 1 < N) *(float4*)&C[(size_t)(ia + 1) * 64 + tc * 4] = make_float4(hi0, hi1, hi2, hi3);
    }
}

// ------- fused layer: h_new = relu(h@w_self + b + sum_e relu(g[src_e] + ea_e@w_edge)) -------
// relies on dst == repeat(arange(N),4): node i's edges are [4i, 4i+4)
__global__ void __launch_bounds__(128) k_layer(const float* __restrict__ H,
                                               const float* __restrict__ G,
                                               const float* __restrict__ Wself,
                                               const float* __restrict__ Wedge,
                                               const float* __restrict__ bl,
                                               const int* __restrict__ src,
                                               const float* __restrict__ ea,
                                               float* __restrict__ Hout, int N) {
    __shared__ float at[64][68];
    __shared__ float ws[64 * 64];
    __shared__ float we_s[256];
    __shared__ float bs[64];
    __shared__ int ss[256];
    __shared__ float eas[1024];
    int tid = threadIdx.x;
    {
        const float4* W4 = (const float4*)Wself;
        float4* ws4 = (float4*)ws;
#pragma unroll
        for (int t = 0; t < 8; t++) ws4[tid + t * 128] = W4[tid + t * 128];
    }
#pragma unroll
    for (int t = 0; t < 2; t++) we_s[tid + t * 128] = Wedge[tid + t * 128];
    if (tid < 64) bs[tid] = bl[tid];
    int i0 = blockIdx.x * 64;
    int e0 = i0 * 4;
    int E = N * 4;
#pragma unroll
    for (int t = 0; t < 2; t++) {
        int idx = tid + t * 128;
        int eg = e0 + idx;
        ss[idx] = (eg < E) ? src[eg] : 0;
    }
#pragma unroll
    for (int t = 0; t < 8; t++) {
        int idx = tid + t * 128;
        eas[idx] = (e0 * 4 + idx < E * 4) ? ea[(size_t)e0 * 4 + idx] : 0.f;
    }
    load_a_tile_T(H, i0, N, at, tid);
    __syncthreads();

    int tr = tid >> 4, tc = tid & 15;
    int r0 = tr * 8;
    ull acc[4][4];
#pragma unroll
    for (int p = 0; p < 4; p++)
#pragma unroll
        for (int j = 0; j < 4; j++) acc[p][j] = 0ULL;

#pragma unroll 8
    for (int k = 0; k < 64; k++) {
        const ull* ap = (const ull*)&at[k][r0];
        ull a0 = ap[0], a1 = ap[1], a2 = ap[2], a3 = ap[3];
        float4 w4 = *(const float4*)&ws[k * 64 + tc * 4];
        ull wx, wy, wz, ww;
        PACKF2(wx, w4.x); PACKF2(wy, w4.y); PACKF2(wz, w4.z); PACKF2(ww, w4.w);
        FFMA2(acc[0][0], a0, wx); FFMA2(acc[0][1], a0, wy);
        FFMA2(acc[0][2], a0, wz); FFMA2(acc[0][3], a0, ww);
        FFMA2(acc[1][0], a1, wx); FFMA2(acc[1][1], a1, wy);
        FFMA2(acc[1][2], a1, wz); FFMA2(acc[1][3], a1, ww);
        FFMA2(acc[2][0], a2, wx); FFMA2(acc[2][1], a2, wy);
        FFMA2(acc[2][2], a2, wz); FFMA2(acc[2][3], a2, ww);
        FFMA2(acc[3][0], a3, wx); FFMA2(acc[3][1], a3, wy);
        FFMA2(acc[3][2], a3, wz); FFMA2(acc[3][3], a3, ww);
    }

    float4 wer[4];
#pragma unroll
    for (int d = 0; d < 4; d++) wer[d] = *(const float4*)&we_s[d * 64 + tc * 4];
    float4 b4 = *(const float4*)&bs[tc * 4];

#pragma unroll
    for (int p = 0; p < 4; p++) {
        float c[2][4];
        UNPACK2(c[0][0], c[1][0], acc[p][0]);
        UNPACK2(c[0][1], c[1][1], acc[p][1]);
        UNPACK2(c[0][2], c[1][2], acc[p][2]);
        UNPACK2(c[0][3], c[1][3], acc[p][3]);
#pragma unroll
        for (int rr = 0; rr < 2; rr++) {
            int row = r0 + 2 * p + rr;
            int i = i0 + row;
            if (i >= N) continue;
            float4 agg = make_float4(0.f, 0.f, 0.f, 0.f);
#pragma unroll
            for (int el = 0; el < 4; el++) {
                int s = ss[row * 4 + el];
                float4 m = *(const float4*)&G[(size_t)s * 64 + tc * 4];
#pragma unroll
                for (int d = 0; d < 4; d++) {
                    float e = eas[(row * 4 + el) * 4 + d];
                    m.x += e * wer[d].x; m.y += e * wer[d].y;
                    m.z += e * wer[d].z; m.w += e * wer[d].w;
                }
                agg.x += fmaxf(m.x, 0.f); agg.y += fmaxf(m.y, 0.f);
                agg.z += fmaxf(m.z, 0.f); agg.w += fmaxf(m.w, 0.f);
            }
            float4 o;
            o.x = fmaxf(c[rr][0] + agg.x + b4.x, 0.f);
            o.y = fmaxf(c[rr][1] + agg.y + b4.y, 0.f);
            o.z = fmaxf(c[rr][2] + agg.z + b4.z, 0.f);
            o.w = fmaxf(c[rr][3] + agg.w + b4.w, 0.f);
            *(float4*)&Hout[(size_t)i * 64 + tc * 4] = o;
        }
    }
}

// -------- emb = h@w_out + b_out ; loc_logit = relu(emb@la_w1+la_b1)@la_w2 + la_b2 --------
__global__ void k_emb(const float* __restrict__ H, const float* __restrict__ Wout,
                      const float* __restrict__ bout, const float* __restrict__ law1,
                      const float* __restrict__ lab1, const float* __restrict__ law2,
                      const float* __restrict__ lab2, float* __restrict__ emb,
                      float* __restrict__ logit, int N) {
    __shared__ float wo[64 * 32];
    __shared__ float w1[32 * 32];
    __shared__ float bo[32], b1[32], w2[32];
    __shared__ float as[8][65];
    __shared__ float es[8][33];
    int tid = threadIdx.x;
    for (int t = tid; t < 2048; t += 256) wo[t] = Wout[t];
    for (int t = tid; t < 1024; t += 256) w1[t] = law1[t];
    if (tid < 32) { bo[tid] = bout[tid]; b1[tid] = lab1[tid]; w2[tid] = law2[tid]; }
    int i0 = blockIdx.x * 8;
#pragma unroll
    for (int t = 0; t < 2; t++) {
        int idx = tid + t * 256;
        int n = idx >> 6, k = idx & 63;
        int i = i0 + n;
        as[n][k] = (i < N) ? H[(size_t)i * 64 + k] : 0.f;
    }
    __syncthreads();
    int n = tid >> 5, j = tid & 31;  // one warp per node
    int i = i0 + n;
    float e = bo[j];
#pragma unroll
    for (int k = 0; k < 64; k++) e += as[n][k] * wo[k * 32 + j];
    es[n][j] = e;
    if (i < N) emb[(size_t)i * 32 + j] = e;
    __syncwarp();
    float a = b1[j];
#pragma unroll
    for (int k = 0; k < 32; k++) a += es[n][k] * w1[k * 32 + j];
    a = fmaxf(a, 0.f);
    float v = a * w2[j];
#pragma unroll
    for (int o = 16; o > 0; o >>= 1) v += __shfl_down_sync(0xffffffffu, v, o);
    if (j == 0 && i < N) logit[i] = v + lab2[0];
}

// -------- per-graph heads: one block per graph --------
__global__ void k_heads(const float* __restrict__ emb, const float* __restrict__ logit,
                        const int* __restrict__ ptr, const int* __restrict__ loc,
                        const int* __restrict__ mut,
                        const float* __restrict__ maw1, const float* __restrict__ mab1,
                        const float* __restrict__ maw2, const float* __restrict__ mab2,
                        const float* __restrict__ lcw1, const float* __restrict__ lcb1,
                        const float* __restrict__ lcw2, const float* __restrict__ lcb2,
                        const float* __restrict__ mcw1, const float* __restrict__ mcb1,
                        const float* __restrict__ mcw2, const float* __restrict__ mcb2,
                        float* __restrict__ out, int B) {
    __shared__ float ls[768];
    __shared__ float red[256];
    __shared__ float red2[256];
    __shared__ float pool[8][33];
    __shared__ float poolr[32];
    __shared__ float selr[32];
    __shared__ float hidm[32];
    int b = blockIdx.x, tid = threadIdx.x;
    int i0 = ptr[b], i1 = ptr[b + 1];
    int cnt = i1 - i0;
    for (int t = tid; t < cnt; t += 256) ls[t] = logit[i0 + t];
    int j = tid & 31, r = tid >> 5;
    float p = 0.f;
    for (int t = r; t < cnt; t += 8) p += emb[(size_t)(i0 + t) * 32 + j];
    pool[r][j] = p;
    __syncthreads();
    if (tid < 32) {
        float s = 0.f;
#pragma unroll
        for (int rr = 0; rr < 8; rr++) s += pool[rr][tid];
        poolr[tid] = s;
    }
    float m = -1e30f;
    for (int t = tid; t < cnt; t += 256) m = fmaxf(m, ls[t]);
    red[tid] = m;
    __syncthreads();
    for (int s = 128; s > 0; s >>= 1) {
        if (tid < s) red[tid] = fmaxf(red[tid], red[tid + s]);
        __syncthreads();
    }
    m = red[0];
    __syncthreads();
    float z = 0.f, sz = 0.f;
    for (int t = tid; t < cnt; t += 256) {
        float zz = ls[t] - m;
        float e = expf(zz);
        z += e; sz += e * zz;
    }
    red[tid] = z; red2[tid] = sz;
    __syncthreads();
    for (int s = 128; s > 0; s >>= 1) {
        if (tid < s) { red[tid] += red[tid + s]; red2[tid] += red2[tid + s]; }
        __syncthreads();
    }
    float Z = red[0], S = red2[0];
    float logZ = logf(Z);
    int gl = i0 + loc[b];
    if (tid < 32) selr[tid] = emb[(size_t)gl * 32 + tid];
    __syncthreads();
    if (tid < 32) {
        float h1 = mab1[tid];
#pragma unroll
        for (int k = 0; k < 32; k++) h1 += selr[k] * maw1[k * 32 + tid];
        hidm[tid] = fmaxf(h1, 0.f);
    }
    __syncthreads();
    if (tid == 0) {
        float lg[4];
        float mm = -1e30f;
#pragma unroll
        for (int q = 0; q < 4; q++) {
            float s = mab2[q];
            for (int k = 0; k < 32; k++) s += hidm[k] * maw2[k * 4 + q];
            lg[q] = s; mm = fmaxf(mm, s);
        }
        float se = 0.f;
#pragma unroll
        for (int q = 0; q < 4; q++) se += expf(lg[q] - mm);
        float lse = logf(se) + mm;
        float ent = 0.f;
#pragma unroll
        for (int q = 0; q < 4; q++) {
            float lp = lg[q] - lse;
            ent -= expf(lp) * lp;
        }
        out[1 * B + b] = lg[mut[b]] - lse;
        out[3 * B + b] = ent;
        out[0 * B + b] = (ls[loc[b]] - m) - logZ;
        out[2 * B + b] = logZ - S / Z;
    }
    if (tid < 32) {
        float h2 = lcb1[tid];
#pragma unroll
        for (int k = 0; k < 32; k++) h2 += poolr[k] * lcw1[k * 32 + tid];
        h2 = fmaxf(h2, 0.f);
        float v = h2 * lcw2[tid];
#pragma unroll
        for (int o = 16; o > 0; o >>= 1) v += __shfl_down_sync(0xffffffffu, v, o);
        if (tid == 0) out[4 * B + b] = v + lcb2[0];
        float h3 = mcb1[tid];
#pragma unroll
        for (int k = 0; k < 32; k++) h3 += selr[k] * mcw1[k * 32 + tid];
        h3 = fmaxf(h3, 0.f);
        float v2 = h3 * mcw2[tid];
#pragma unroll
        for (int o = 16; o > 0; o >>= 1) v2 += __shfl_down_sync(0xffffffffu, v2, o);
        if (tid == 0) out[5 * B + b] = v2 + mcb2[0];
    }
}

extern "C" void kernel_launch(void* const* d_in, const int* in_sizes, int n_in,
                              void* d_out, int out_size) {
    const float* x      = (const float*)d_in[0];
    const float* eattr  = (const float*)d_in[1];
    const int*   ei     = (const int*)d_in[2];
    const int*   ptr    = (const int*)d_in[4];
    const int*   loc    = (const int*)d_in[5];
    const int*   mut    = (const int*)d_in[6];
    const float* w_in   = (const float*)d_in[7];
    const float* b_in   = (const float*)d_in[8];
    const float* w_self = (const float*)d_in[9];
    const float* w_nb   = (const float*)d_in[10];
    const float* w_edge = (const float*)d_in[11];
    const float* b_l    = (const float*)d_in[12];
    const float* w_out  = (const float*)d_in[13];
    const float* b_out  = (const float*)d_in[14];
    const float* la_w1  = (const float*)d_in[15];
    const float* la_b1  = (const float*)d_in[16];
    const float* la_w2  = (const float*)d_in[17];
    const float* la_b2  = (const float*)d_in[18];
    const float* ma_w1  = (const float*)d_in[19];
    const float* ma_b1  = (const float*)d_in[20];
    const float* ma_w2  = (const float*)d_in[21];
    const float* ma_b2  = (const float*)d_in[22];
    const float* lc_w1  = (const float*)d_in[23];
    const float* lc_b1  = (const float*)d_in[24];
    const float* lc_w2  = (const float*)d_in[25];
    const float* lc_b2  = (const float*)d_in[26];
    const float* mc_w1  = (const float*)d_in[27];
    const float* mc_b1  = (const float*)d_in[28];
    const float* mc_w2  = (const float*)d_in[29];
    const float* mc_b2  = (const float*)d_in[30];
    float* out = (float*)d_out;

    int N = in_sizes[0] / 8;
    int B = in_sizes[4] - 1;
    const int* src = ei;  // edge_index row 0

    float *hA, *hB, *gG, *embp, *lg;
    cudaGetSymbolAddress((void**)&hA, g_bufA);
    cudaGetSymbolAddress((void**)&hB, g_bufB);
    cudaGetSymbolAddress((void**)&gG, g_bufG);
    cudaGetSymbolAddress((void**)&embp, g_embv);
    cudaGetSymbolAddress((void**)&lg, g_logit);

    float* hin = hA;
    float* hout = hB;
    int gb = (N + 63) / 64;
    k_in<<<(N + 3) / 4, 256>>>(x, w_in, b_in, hin, N);
    for (int l = 0; l < 3; l++) {
        k_nbmm<<<gb, 128>>>(hin, w_nb + l * 4096, gG, N);
        k_layer<<<gb, 128>>>(hin, gG, w_self + l * 4096, w_edge + l * 256,
                             b_l + l * 64, src, eattr, hout, N);
        float* t = hin; hin = hout; hout = t;
    }
    k_emb<<<(N + 7) / 8, 256>>>(hin, w_out, b_out, la_w1, la_b1, la_w2, la_b2,
                                embp, lg, N);
    k_heads<<<B, 256>>>(embp, lg, ptr, loc, mut,
                        ma_w1, ma_b1, ma_w2, ma_b2,
                        lc_w1, lc_b1, lc_w2, lc_b2,
                        mc_w1, mc_b1, mc_w2, mc_b2,
                        out, B);
}

// round 5
// speedup vs baseline: 2.1547x; 1.2148x over previous
#include <cuda_runtime.h>
#include <math.h>

#define NMAX 393216   // 768 * 512 upper bound on total nodes
#define AT_S 134      // transposed tile stride (even for 8B ull loads)

typedef unsigned long long ull;

// scratch (allocation-free rule: device globals)
__device__ float g_bufA[NMAX * 64];
__device__ float g_bufB[NMAX * 64];
__device__ float g_gA[NMAX * 64];
__device__ float g_gB[NMAX * 64];
__device__ float g_embv[NMAX * 32];
__device__ float g_logit[NMAX];

// dynamic smem layout offsets (bytes)
#define OFF_WS   34304              // at = 64*134*4
#define OFF_X2   (OFF_WS + 16384)   // after ws[4096]
#define SM_IN_G  (OFF_X2 + 4608 + 256)          // xs[128][9] + bs[64]
#define SM_LAYER (OFF_X2 + 1024 + 256)          // wes[256] + bs[64]
#define SM_L2    (OFF_X2 + 1024 + 256 + 128)    // wes + bs + bos[32]

// packed fp32x2 helpers (Blackwell)
#define FFMA2(d, a, b) asm("fma.rn.f32x2 %0, %1, %2, %0;" : "+l"(d) : "l"(a), "l"(b))
#define PACKF2(d, x)   asm("mov.b64 %0, {%1, %1};" : "=l"(d) : "f"(x))
#define UNPACK2(lo, hi, p) asm("mov.b64 {%0, %1}, %2;" : "=f"(lo), "=f"(hi) : "l"(p))

// ---- core 128x64x64 mma: 8 rows x 8 cols per thread, rowpair-packed f32x2 ----
__device__ __forceinline__ void mma8(const float (*at)[AT_S], const float* __restrict__ ws,
                                     int r0, int c0, ull acc[4][8]) {
#pragma unroll
    for (int p = 0; p < 4; p++)
#pragma unroll
        for (int c = 0; c < 8; c++) acc[p][c] = 0ULL;
#pragma unroll 8
    for (int k = 0; k < 64; k++) {
        const ull* ap = (const ull*)&at[k][r0];
        ull a0 = ap[0], a1 = ap[1], a2 = ap[2], a3 = ap[3];
        const float4* wp = (const float4*)&ws[k * 64 + c0];
        float4 wA = wp[0], wB = wp[1];
        ull w0, w1, w2, w3, w4, w5, w6, w7;
        PACKF2(w0, wA.x); PACKF2(w1, wA.y); PACKF2(w2, wA.z); PACKF2(w3, wA.w);
        PACKF2(w4, wB.x); PACKF2(w5, wB.y); PACKF2(w6, wB.z); PACKF2(w7, wB.w);
        FFMA2(acc[0][0], a0, w0); FFMA2(acc[0][1], a0, w1);
        FFMA2(acc[0][2], a0, w2); FFMA2(acc[0][3], a0, w3);
        FFMA2(acc[0][4], a0, w4); FFMA2(acc[0][5], a0, w5);
        FFMA2(acc[0][6], a0, w6); FFMA2(acc[0][7], a0, w7);
        FFMA2(acc[1][0], a1, w0); FFMA2(acc[1][1], a1, w1);
        FFMA2(acc[1][2], a1, w2); FFMA2(acc[1][3], a1, w3);
        FFMA2(acc[1][4], a1, w4); FFMA2(acc[1][5], a1, w5);
        FFMA2(acc[1][6], a1, w6); FFMA2(acc[1][7], a1, w7);
        FFMA2(acc[2][0], a2, w0); FFMA2(acc[2][1], a2, w1);
        FFMA2(acc[2][2], a2, w2); FFMA2(acc[2][3], a2, w3);
        FFMA2(acc[2][4], a2, w4); FFMA2(acc[2][5], a2, w5);
        FFMA2(acc[2][6], a2, w6); FFMA2(acc[2][7], a2, w7);
        FFMA2(acc[3][0], a3, w0); FFMA2(acc[3][1], a3, w1);
        FFMA2(acc[3][2], a3, w2); FFMA2(acc[3][3], a3, w3);
        FFMA2(acc[3][4], a3, w4); FFMA2(acc[3][5], a3, w5);
        FFMA2(acc[3][6], a3, w6); FFMA2(acc[3][7], a3, w7);
    }
}

// ---- 128x32x64 mma: 8 rows x 4 cols per thread (ws row stride 32) ----
__device__ __forceinline__ void mma4(const float (*at)[AT_S], const float* __restrict__ ws,
                                     int r0, int c0, ull acc[4][4]) {
#pragma unroll
    for (int p = 0; p < 4; p++)
#pragma unroll
        for (int c = 0; c < 4; c++) acc[p][c] = 0ULL;
#pragma unroll 8
    for (int k = 0; k < 64; k++) {
        const ull* ap = (const ull*)&at[k][r0];
        ull a0 = ap[0], a1 = ap[1], a2 = ap[2], a3 = ap[3];
        float4 wA = *(const float4*)&ws[k * 32 + c0];
        ull w0, w1, w2, w3;
        PACKF2(w0, wA.x); PACKF2(w1, wA.y); PACKF2(w2, wA.z); PACKF2(w3, wA.w);
        FFMA2(acc[0][0], a0, w0); FFMA2(acc[0][1], a0, w1);
        FFMA2(acc[0][2], a0, w2); FFMA2(acc[0][3], a0, w3);
        FFMA2(acc[1][0], a1, w0); FFMA2(acc[1][1], a1, w1);
        FFMA2(acc[1][2], a1, w2); FFMA2(acc[1][3], a1, w3);
        FFMA2(acc[2][0], a2, w0); FFMA2(acc[2][1], a2, w1);
        FFMA2(acc[2][2], a2, w2); FFMA2(acc[2][3], a2, w3);
        FFMA2(acc[3][0], a3, w0); FFMA2(acc[3][1], a3, w1);
        FFMA2(acc[3][2], a3, w2); FFMA2(acc[3][3], a3, w3);
    }
}

// ---- stage a 128x64 row-major global tile transposed into at[k][row] ----
__device__ __forceinline__ void stage_tile(const float* __restrict__ A, int i0, int N,
                                           float (*at)[AT_S], int tid) {
    int i = i0 + tid;
    const float4* A4 = (const float4*)A;
#pragma unroll
    for (int q = 0; q < 16; q++) {
        float4 v = (i < N) ? A4[(size_t)i * 16 + q] : make_float4(0.f, 0.f, 0.f, 0.f);
        at[q * 4 + 0][tid] = v.x;
        at[q * 4 + 1][tid] = v.y;
        at[q * 4 + 2][tid] = v.z;
        at[q * 4 + 3][tid] = v.w;
    }
}

// =============== k_in_g: h0 = relu(x@w_in+b); G0 = h0 @ w_nb[0] ===============
__global__ void __launch_bounds__(128) k_in_g(const float* __restrict__ x,
                                              const float* __restrict__ w_in,
                                              const float* __restrict__ b_in,
                                              const float* __restrict__ wnb0,
                                              float* __restrict__ H0,
                                              float* __restrict__ G0, int N) {
    extern __shared__ __align__(16) char sm[];
    float (*at)[AT_S] = (float (*)[AT_S])sm;
    float* ws = (float*)(sm + OFF_WS);
    float (*xs)[9] = (float (*)[9])(sm + OFF_X2);
    float* bs = (float*)(sm + OFF_X2 + 4608);
    int tid = threadIdx.x;
    int i0 = blockIdx.x * 128;
    for (int t = tid; t < 512; t += 128) ws[t] = w_in[t];
    if (tid < 64) bs[tid] = b_in[tid];
    {
        int i = i0 + tid;
        float4 v0, v1;
        if (i < N) { v0 = ((const float4*)x)[i * 2]; v1 = ((const float4*)x)[i * 2 + 1]; }
        else { v0 = make_float4(0.f, 0.f, 0.f, 0.f); v1 = v0; }
        xs[tid][0] = v0.x; xs[tid][1] = v0.y; xs[tid][2] = v0.z; xs[tid][3] = v0.w;
        xs[tid][4] = v1.x; xs[tid][5] = v1.y; xs[tid][6] = v1.z; xs[tid][7] = v1.w;
    }
    __syncthreads();
    int tr = tid >> 3, tc = tid & 7;
    int r0 = tr * 8, c0 = tc * 8;
    float acc[8][8];
#pragma unroll
    for (int r = 0; r < 8; r++)
#pragma unroll
        for (int c = 0; c < 8; c++) acc[r][c] = bs[c0 + c];
#pragma unroll
    for (int k = 0; k < 8; k++) {
        float w8[8];
#pragma unroll
        for (int c = 0; c < 8; c++) w8[c] = ws[k * 64 + c0 + c];
#pragma unroll
        for (int r = 0; r < 8; r++) {
            float a = xs[r0 + r][k];
#pragma unroll
            for (int c = 0; c < 8; c++) acc[r][c] += a * w8[c];
        }
    }
#pragma unroll
    for (int r = 0; r < 8; r++) {
        int row = r0 + r;
        int i = i0 + row;
#pragma unroll
        for (int c = 0; c < 8; c++) acc[r][c] = fmaxf(acc[r][c], 0.f);
        if (i < N) {
            *(float4*)&H0[(size_t)i * 64 + c0] = make_float4(acc[r][0], acc[r][1], acc[r][2], acc[r][3]);
            *(float4*)&H0[(size_t)i * 64 + c0 + 4] = make_float4(acc[r][4], acc[r][5], acc[r][6], acc[r][7]);
        }
#pragma unroll
        for (int c = 0; c < 8; c++) at[c0 + c][row] = acc[r][c];
    }
    __syncthreads();
    for (int t = tid; t < 4096; t += 128) ws[t] = wnb0[t];
    __syncthreads();
    ull acc2[4][8];
    mma8(at, ws, r0, c0, acc2);
#pragma unroll
    for (int p = 0; p < 4; p++) {
        float lo[8], hi[8];
#pragma unroll
        for (int c = 0; c < 8; c++) UNPACK2(lo[c], hi[c], acc2[p][c]);
        int ia = i0 + r0 + 2 * p;
        if (ia < N) {
            *(float4*)&G0[(size_t)ia * 64 + c0] = make_float4(lo[0], lo[1], lo[2], lo[3]);
            *(float4*)&G0[(size_t)ia * 64 + c0 + 4] = make_float4(lo[4], lo[5], lo[6], lo[7]);
        }
        if (ia + 1 < N) {
            *(float4*)&G0[(size_t)(ia + 1) * 64 + c0] = make_float4(hi[0], hi[1], hi[2], hi[3]);
            *(float4*)&G0[(size_t)(ia + 1) * 64 + c0 + 4] = make_float4(hi[4], hi[5], hi[6], hi[7]);
        }
    }
}

// === fused layer (l=0,1): h' = relu(h@wself + b + agg); G' = h' @ wnb_next ===
// relies on dst == repeat(arange(N),4): node i's edges are [4i, 4i+4)
__global__ void __launch_bounds__(128) k_layer_f(const float* __restrict__ H,
                                                 const float* __restrict__ G,
                                                 const float* __restrict__ wself,
                                                 const float* __restrict__ wedge,
                                                 const float* __restrict__ bl,
                                                 const int* __restrict__ src,
                                                 const float* __restrict__ ea,
                                                 const float* __restrict__ wnb_next,
                                                 float* __restrict__ Hout,
                                                 float* __restrict__ Gnext, int N) {
    extern __shared__ __align__(16) char sm[];
    float (*at)[AT_S] = (float (*)[AT_S])sm;
    float* ws = (float*)(sm + OFF_WS);
    float* wes = (float*)(sm + OFF_X2);
    float* bs = (float*)(sm + OFF_X2 + 1024);
    int tid = threadIdx.x;
    int i0 = blockIdx.x * 128;
    for (int t = tid; t < 4096; t += 128) ws[t] = wself[t];
    for (int t = tid; t < 256; t += 128) wes[t] = wedge[t];
    if (tid < 64) bs[tid] = bl[tid];
    stage_tile(H, i0, N, at, tid);
    __syncthreads();

    int tr = tid >> 3, tc = tid & 7;
    int r0 = tr * 8, c0 = tc * 8;
    ull acc[4][8];
    mma8(at, ws, r0, c0, acc);
    __syncthreads();   // GEMM1 done reading at/ws

    for (int t = tid; t < 4096; t += 128) ws[t] = wnb_next[t];

#pragma unroll
    for (int p = 0; p < 4; p++) {
        float v[2][8];
#pragma unroll
        for (int c = 0; c < 8; c++) UNPACK2(v[0][c], v[1][c], acc[p][c]);
#pragma unroll
        for (int rr = 0; rr < 2; rr++) {
            int row = r0 + 2 * p + rr;
            int i = i0 + row;
            if (i < N) {
                int4 s4 = *(const int4*)&src[4 * i];
                const float4* eap = (const float4*)&ea[(size_t)16 * i];
                float4 e4[4] = {eap[0], eap[1], eap[2], eap[3]};
                int sarr[4] = {s4.x, s4.y, s4.z, s4.w};
                float agg[8] = {0.f, 0.f, 0.f, 0.f, 0.f, 0.f, 0.f, 0.f};
#pragma unroll
                for (int e = 0; e < 4; e++) {
                    const float* gp = &G[(size_t)sarr[e] * 64 + c0];
                    float4 ga = *(const float4*)gp;
                    float4 gb = *(const float4*)(gp + 4);
                    float m[8] = {ga.x, ga.y, ga.z, ga.w, gb.x, gb.y, gb.z, gb.w};
                    float ex = e4[e].x, ey = e4[e].y, ez = e4[e].z, ew = e4[e].w;
#pragma unroll
                    for (int c = 0; c < 8; c++)
                        m[c] += ex * wes[c0 + c] + ey * wes[64 + c0 + c]
                              + ez * wes[128 + c0 + c] + ew * wes[192 + c0 + c];
#pragma unroll
                    for (int c = 0; c < 8; c++) agg[c] += fmaxf(m[c], 0.f);
                }
                float o[8];
#pragma unroll
                for (int c = 0; c < 8; c++) o[c] = fmaxf(v[rr][c] + agg[c] + bs[c0 + c], 0.f);
                *(float4*)&Hout[(size_t)i * 64 + c0] = make_float4(o[0], o[1], o[2], o[3]);
                *(float4*)&Hout[(size_t)i * 64 + c0 + 4] = make_float4(o[4], o[5], o[6], o[7]);
#pragma unroll
                for (int c = 0; c < 8; c++) at[c0 + c][row] = o[c];
            }
        }
    }
    __syncthreads();

    ull acc2[4][8];
    mma8(at, ws, r0, c0, acc2);
#pragma unroll
    for (int p = 0; p < 4; p++) {
        float lo[8], hi[8];
#pragma unroll
        for (int c = 0; c < 8; c++) UNPACK2(lo[c], hi[c], acc2[p][c]);
        int ia = i0 + r0 + 2 * p;
        if (ia < N) {
            *(float4*)&Gnext[(size_t)ia * 64 + c0] = make_float4(lo[0], lo[1], lo[2], lo[3]);
            *(float4*)&Gnext[(size_t)ia * 64 + c0 + 4] = make_float4(lo[4], lo[5], lo[6], lo[7]);
        }
        if (ia + 1 < N) {
            *(float4*)&Gnext[(size_t)(ia + 1) * 64 + c0] = make_float4(hi[0], hi[1], hi[2], hi[3]);
            *(float4*)&Gnext[(size_t)(ia + 1) * 64 + c0 + 4] = make_float4(hi[4], hi[5], hi[6], hi[7]);
        }
    }
}

// === last layer: h3 = relu(...); emb = h3@wout + bout; logit = MLP(emb) ===
__global__ void __launch_bounds__(128) k_l2(const float* __restrict__ H,
                                            const float* __restrict__ G,
                                            const float* __restrict__ wself,
                                            const float* __restrict__ wedge,
                                            const float* __restrict__ bl,
                                            const int* __restrict__ src,
                                            const float* __restrict__ ea,
                                            const float* __restrict__ wout,
                                            const float* __restrict__ bout,
                                            const float* __restrict__ law1,
                                            const float* __restrict__ lab1,
                                            const float* __restrict__ law2,
                                            const float* __restrict__ lab2,
                                            float* __restrict__ emb,
                                            float* __restrict__ logit, int N) {
    extern __shared__ __align__(16) char sm[];
    float (*at)[AT_S] = (float (*)[AT_S])sm;
    float* ws = (float*)(sm + OFF_WS);
    float* wes = (float*)(sm + OFF_X2);
    float* bs = (float*)(sm + OFF_X2 + 1024);
    float* bos = (float*)(sm + OFF_X2 + 1024 + 256);
    int tid = threadIdx.x;
    int i0 = blockIdx.x * 128;
    for (int t = tid; t < 4096; t += 128) ws[t] = wself[t];
    for (int t = tid; t < 256; t += 128) wes[t] = wedge[t];
    if (tid < 64) bs[tid] = bl[tid];
    if (tid < 32) bos[tid] = bout[tid];
    stage_tile(H, i0, N, at, tid);
    __syncthreads();

    int tr = tid >> 3, tc = tid & 7;
    int r0 = tr * 8, c0 = tc * 8;
    ull acc[4][8];
    mma8(at, ws, r0, c0, acc);
    __syncthreads();

    // ws: [0..2047]=wout, [2048..3071]=la_w1, [3072..3103]=la_b1, [3104..3135]=la_w2
    for (int t = tid; t < 2048; t += 128) ws[t] = wout[t];
    for (int t = tid; t < 1024; t += 128) ws[2048 + t] = law1[t];
    if (tid < 32) { ws[3072 + tid] = lab1[tid]; ws[3104 + tid] = law2[tid]; }

#pragma unroll
    for (int p = 0; p < 4; p++) {
        float v[2][8];
#pragma unroll
        for (int c = 0; c < 8; c++) UNPACK2(v[0][c], v[1][c], acc[p][c]);
#pragma unroll
        for (int rr = 0; rr < 2; rr++) {
            int row = r0 + 2 * p + rr;
            int i = i0 + row;
            if (i < N) {
                int4 s4 = *(const int4*)&src[4 * i];
                const float4* eap = (const float4*)&ea[(size_t)16 * i];
                float4 e4[4] = {eap[0], eap[1], eap[2], eap[3]};
                int sarr[4] = {s4.x, s4.y, s4.z, s4.w};
                float agg[8] = {0.f, 0.f, 0.f, 0.f, 0.f, 0.f, 0.f, 0.f};
#pragma unroll
                for (int e = 0; e < 4; e++) {
                    const float* gp = &G[(size_t)sarr[e] * 64 + c0];
                    float4 ga = *(const float4*)gp;
                    float4 gb = *(const float4*)(gp + 4);
                    float m[8] = {ga.x, ga.y, ga.z, ga.w, gb.x, gb.y, gb.z, gb.w};
                    float ex = e4[e].x, ey = e4[e].y, ez = e4[e].z, ew = e4[e].w;
#pragma unroll
                    for (int c = 0; c < 8; c++)
                        m[c] += ex * wes[c0 + c] + ey * wes[64 + c0 + c]
                              + ez * wes[128 + c0 + c] + ew * wes[192 + c0 + c];
#pragma unroll
                    for (int c = 0; c < 8; c++) agg[c] += fmaxf(m[c], 0.f);
                }
#pragma unroll
                for (int c = 0; c < 8; c++) {
                    float o = fmaxf(v[rr][c] + agg[c] + bs[c0 + c], 0.f);
                    at[c0 + c][row] = o;
                }
            }
        }
    }
    __syncthreads();

    // emb GEMM: 128x32
    int c04 = tc * 4;
    ull acc2[4][4];
    mma4(at, ws, r0, c04, acc2);
    __syncthreads();   // everyone done reading at -> reuse as em[row*33+c]

    float* em = &at[0][0];
#pragma unroll
    for (int p = 0; p < 4; p++) {
        float lo[4], hi[4];
#pragma unroll
        for (int c = 0; c < 4; c++) UNPACK2(lo[c], hi[c], acc2[p][c]);
        int rowa = r0 + 2 * p;
        int ia = i0 + rowa;
#pragma unroll
        for (int c = 0; c < 4; c++) { lo[c] += bos[c04 + c]; hi[c] += bos[c04 + c]; }
        if (ia < N)
            *(float4*)&emb[(size_t)ia * 32 + c04] = make_float4(lo[0], lo[1], lo[2], lo[3]);
        if (ia + 1 < N)
            *(float4*)&emb[(size_t)(ia + 1) * 32 + c04] = make_float4(hi[0], hi[1], hi[2], hi[3]);
#pragma unroll
        for (int c = 0; c < 4; c++) {
            em[rowa * 33 + c04 + c] = lo[c];
            em[(rowa + 1) * 33 + c04 + c] = hi[c];
        }
    }
    __syncthreads();

    // per-node location logit MLP: one thread per row
    int i = i0 + tid;
    if (i < N) {
        float er[32];
#pragma unroll
        for (int k = 0; k < 32; k++) er[k] = em[tid * 33 + k];
        float vsum = 0.f;
#pragma unroll 4
        for (int j = 0; j < 32; j++) {
            float s = ws[3072 + j];
#pragma unroll
            for (int k = 0; k < 32; k++) s += er[k] * ws[2048 + k * 32 + j];
            vsum += fmaxf(s, 0.f) * ws[3104 + j];
        }
        logit[i] = vsum + lab2[0];
    }
}

// -------- per-graph heads: one block per graph --------
__global__ void k_heads(const float* __restrict__ emb, const float* __restrict__ logit,
                        const int* __restrict__ ptr, const int* __restrict__ loc,
                        const int* __restrict__ mut,
                        const float* __restrict__ maw1, const float* __restrict__ mab1,
                        const float* __restrict__ maw2, const float* __restrict__ mab2,
                        const float* __restrict__ lcw1, const float* __restrict__ lcb1,
                        const float* __restrict__ lcw2, const float* __restrict__ lcb2,
                        const float* __restrict__ mcw1, const float* __restrict__ mcb1,
                        const float* __restrict__ mcw2, const float* __restrict__ mcb2,
                        float* __restrict__ out, int B) {
    __shared__ float ls[768];
    __shared__ float red[256];
    __shared__ float red2[256];
    __shared__ float pool[8][33];
    __shared__ float poolr[32];
    __shared__ float selr[32];
    __shared__ float hidm[32];
    int b = blockIdx.x, tid = threadIdx.x;
    int i0 = ptr[b], i1 = ptr[b + 1];
    int cnt = i1 - i0;
    for (int t = tid; t < cnt; t += 256) ls[t] = logit[i0 + t];
    int j = tid & 31, r = tid >> 5;
    float p = 0.f;
    for (int t = r; t < cnt; t += 8) p += emb[(size_t)(i0 + t) * 32 + j];
    pool[r][j] = p;
    __syncthreads();
    if (tid < 32) {
        float s = 0.f;
#pragma unroll
        for (int rr = 0; rr < 8; rr++) s += pool[rr][tid];
        poolr[tid] = s;
    }
    float m = -1e30f;
    for (int t = tid; t < cnt; t += 256) m = fmaxf(m, ls[t]);
    red[tid] = m;
    __syncthreads();
    for (int s = 128; s > 0; s >>= 1) {
        if (tid < s) red[tid] = fmaxf(red[tid], red[tid + s]);
        __syncthreads();
    }
    m = red[0];
    __syncthreads();
    float z = 0.f, sz = 0.f;
    for (int t = tid; t < cnt; t += 256) {
        float zz = ls[t] - m;
        float e = expf(zz);
        z += e; sz += e * zz;
    }
    red[tid] = z; red2[tid] = sz;
    __syncthreads();
    for (int s = 128; s > 0; s >>= 1) {
        if (tid < s) { red[tid] += red[tid + s]; red2[tid] += red2[tid + s]; }
        __syncthreads();
    }
    float Z = red[0], S = red2[0];
    float logZ = logf(Z);
    int gl = i0 + loc[b];
    if (tid < 32) selr[tid] = emb[(size_t)gl * 32 + tid];
    __syncthreads();
    if (tid < 32) {
        float h1 = mab1[tid];
#pragma unroll
        for (int k = 0; k < 32; k++) h1 += selr[k] * maw1[k * 32 + tid];
        hidm[tid] = fmaxf(h1, 0.f);
    }
    __syncthreads();
    if (tid == 0) {
        float lg[4];
        float mm = -1e30f;
#pragma unroll
        for (int q = 0; q < 4; q++) {
            float s = mab2[q];
            for (int k = 0; k < 32; k++) s += hidm[k] * maw2[k * 4 + q];
            lg[q] = s; mm = fmaxf(mm, s);
        }
        float se = 0.f;
#pragma unroll
        for (int q = 0; q < 4; q++) se += expf(lg[q] - mm);
        float lse = logf(se) + mm;
        float ent = 0.f;
#pragma unroll
        for (int q = 0; q < 4; q++) {
            float lp = lg[q] - lse;
            ent -= expf(lp) * lp;
        }
        out[1 * B + b] = lg[mut[b]] - lse;
        out[3 * B + b] = ent;
        out[0 * B + b] = (ls[loc[b]] - m) - logZ;
        out[2 * B + b] = logZ - S / Z;
    }
    if (tid < 32) {
        float h2 = lcb1[tid];
#pragma unroll
        for (int k = 0; k < 32; k++) h2 += poolr[k] * lcw1[k * 32 + tid];
        h2 = fmaxf(h2, 0.f);
        float v = h2 * lcw2[tid];
#pragma unroll
        for (int o = 16; o > 0; o >>= 1) v += __shfl_down_sync(0xffffffffu, v, o);
        if (tid == 0) out[4 * B + b] = v + lcb2[0];
        float h3 = mcb1[tid];
#pragma unroll
        for (int k = 0; k < 32; k++) h3 += selr[k] * mcw1[k * 32 + tid];
        h3 = fmaxf(h3, 0.f);
        float v2 = h3 * mcw2[tid];
#pragma unroll
        for (int o = 16; o > 0; o >>= 1) v2 += __shfl_down_sync(0xffffffffu, v2, o);
        if (tid == 0) out[5 * B + b] = v2 + mcb2[0];
    }
}

extern "C" void kernel_launch(void* const* d_in, const int* in_sizes, int n_in,
                              void* d_out, int out_size) {
    const float* x      = (const float*)d_in[0];
    const float* eattr  = (const float*)d_in[1];
    const int*   ei     = (const int*)d_in[2];
    const int*   ptr    = (const int*)d_in[4];
    const int*   loc    = (const int*)d_in[5];
    const int*   mut    = (const int*)d_in[6];
    const float* w_in   = (const float*)d_in[7];
    const float* b_in   = (const float*)d_in[8];
    const float* w_self = (const float*)d_in[9];
    const float* w_nb   = (const float*)d_in[10];
    const float* w_edge = (const float*)d_in[11];
    const float* b_l    = (const float*)d_in[12];
    const float* w_out  = (const float*)d_in[13];
    const float* b_out  = (const float*)d_in[14];
    const float* la_w1  = (const float*)d_in[15];
    const float* la_b1  = (const float*)d_in[16];
    const float* la_w2  = (const float*)d_in[17];
    const float* la_b2  = (const float*)d_in[18];
    const float* ma_w1  = (const float*)d_in[19];
    const float* ma_b1  = (const float*)d_in[20];
    const float* ma_w2  = (const float*)d_in[21];
    const float* ma_b2  = (const float*)d_in[22];
    const float* lc_w1  = (const float*)d_in[23];
    const float* lc_b1  = (const float*)d_in[24];
    const float* lc_w2  = (const float*)d_in[25];
    const float* lc_b2  = (const float*)d_in[26];
    const float* mc_w1  = (const float*)d_in[27];
    const float* mc_b1  = (const float*)d_in[28];
    const float* mc_w2  = (const float*)d_in[29];
    const float* mc_b2  = (const float*)d_in[30];
    float* out = (float*)d_out;

    int N = in_sizes[0] / 8;
    int B = in_sizes[4] - 1;
    const int* src = ei;  // edge_index row 0

    float *hA, *hB, *gA, *gB, *embp, *lg;
    cudaGetSymbolAddress((void**)&hA, g_bufA);
    cudaGetSymbolAddress((void**)&hB, g_bufB);
    cudaGetSymbolAddress((void**)&gA, g_gA);
    cudaGetSymbolAddress((void**)&gB, g_gB);
    cudaGetSymbolAddress((void**)&embp, g_embv);
    cudaGetSymbolAddress((void**)&lg, g_logit);

    cudaFuncSetAttribute(k_in_g, cudaFuncAttributeMaxDynamicSharedMemorySize, SM_IN_G);
    cudaFuncSetAttribute(k_layer_f, cudaFuncAttributeMaxDynamicSharedMemorySize, SM_LAYER);
    cudaFuncSetAttribute(k_l2, cudaFuncAttributeMaxDynamicSharedMemorySize, SM_L2);

    int gb = (N + 127) / 128;
    k_in_g<<<gb, 128, SM_IN_G>>>(x, w_in, b_in, w_nb, hA, gA, N);
    k_layer_f<<<gb, 128, SM_LAYER>>>(hA, gA, w_self, w_edge, b_l, src, eattr,
                                     w_nb + 4096, hB, gB, N);
    k_layer_f<<<gb, 128, SM_LAYER>>>(hB, gB, w_self + 4096, w_edge + 256, b_l + 64, src, eattr,
                                     w_nb + 8192, hA, gA, N);
    k_l2<<<gb, 128, SM_L2>>>(hA, gA, w_self + 8192, w_edge + 512, b_l + 128, src, eattr,
                             w_out, b_out, la_w1, la_b1, la_w2, la_b2, embp, lg, N);
    k_heads<<<B, 256>>>(embp, lg, ptr, loc, mut,
                        ma_w1, ma_b1, ma_w2, ma_b2,
                        lc_w1, lc_b1, lc_w2, lc_b2,
                        mc_w1, mc_b1, mc_w2, mc_b2,
                        out, B);
}